// round 4
// baseline (speedup 1.0000x reference)
#include <cuda_runtime.h>
#include <math.h>

#define NN 50000
#define NE 400000

// ---------------- scratch (device globals; allocation-free) ----------------
__device__ __align__(16) float g_act0[NN * 256];
__device__ __align__(16) float g_act1[NN * 256];
__device__ __align__(16) float g_h[NN * 256];
__device__ __align__(16) float g_acc[NN * 256];
__device__ float g_dinv[NN];
__device__ int   g_deg[NN];
__device__ int2  g_edges[NE];   // decoded (src, dst)
__device__ int   g_is64;

// ---------------- edge dtype sniff + decode ----------------
__global__ void k_detect(const int* __restrict__ e) {
    // int64 little-endian with values < 2^31: every odd 32-bit word is 0.
    int all0 = 1;
    for (int i = 0; i < 128; i++)
        if (e[2 * i + 1] != 0) { all0 = 0; break; }
    g_is64 = all0;
}

__global__ void k_prep(const int* __restrict__ e) {
    int i = blockIdx.x * 256 + threadIdx.x;
    if (i >= NE) return;
    int s, d;
    if (g_is64) {               // int64 layout: [2*NE] int64 values
        s = e[2 * i];
        d = e[2 * (NE + i)];
    } else {                    // int32 layout: [2*NE] int32 values
        s = e[i];
        d = e[NE + i];
    }
    // defensive clamp: never trap, even if the dtype guess is wrong
    s = min(max(s, 0), NN - 1);
    d = min(max(d, 0), NN - 1);
    g_edges[i] = make_int2(s, d);
}

// ---------------- degree / dinv ----------------
__global__ void k_zero_deg() {
    int i = blockIdx.x * 256 + threadIdx.x;
    if (i < NN) g_deg[i] = 0;
}

__global__ void k_deg() {
    int i = blockIdx.x * 256 + threadIdx.x;
    if (i < NE) atomicAdd(&g_deg[g_edges[i].y], 1);
}

__global__ void k_dinv() {
    int i = blockIdx.x * 256 + threadIdx.x;
    if (i < NN) g_dinv[i] = rsqrtf((float)(g_deg[i] + 1));  // +1 self loop
}

__global__ void k_zero_acc(int n4) {
    int i = blockIdx.x * blockDim.x + threadIdx.x;
    int st = gridDim.x * blockDim.x;
    float4* p = (float4*)g_acc;
    float4 z = make_float4(0.f, 0.f, 0.f, 0.f);
    for (; i < n4; i += st) p[i] = z;
}

// ---------------- GEMM:  g_h[n,c] = dinv[n] * sum_k A[n,k] * W[k,c] --------
#define BM 128
#define BN 64
#define BK 16

__global__ __launch_bounds__(256) void k_gemm(
    const float* __restrict__ Aext, int tagA,
    const float* __restrict__ W, int K, int C, int Cpad)
{
    const float* A = (tagA == 1) ? g_act0 : (tagA == 2) ? g_act1 : Aext;
    float* H = g_h;

    __shared__ float As[BK][132];
    __shared__ float Ws[BK][BN];

    const int tid = threadIdx.x;
    const int tx = tid & 15;
    const int ty = tid >> 4;
    const int row0 = blockIdx.y * BM;
    const int col0 = blockIdx.x * BN;

    float acc[8][4];
#pragma unroll
    for (int i = 0; i < 8; i++)
#pragma unroll
        for (int j = 0; j < 4; j++) acc[i][j] = 0.f;

    for (int kt = 0; kt < K; kt += BK) {
#pragma unroll
        for (int s = 0; s < 8; s++) {
            int l = tid + s * 256;
            int r = l >> 4;
            int k = l & 15;
            int grow = row0 + r;
            int gk = kt + k;
            float v = 0.f;
            if (grow < NN && gk < K) v = A[(size_t)grow * K + gk];
            As[k][r] = v;
        }
#pragma unroll
        for (int s = 0; s < 4; s++) {
            int l = tid + s * 256;
            int kr = l >> 6;
            int c  = l & 63;
            int gk = kt + kr;
            int gc = col0 + c;
            float v = 0.f;
            if (gk < K && gc < C) v = W[(size_t)gk * C + gc];
            Ws[kr][c] = v;
        }
        __syncthreads();

#pragma unroll
        for (int kk = 0; kk < BK; kk++) {
            float4 a0 = *(const float4*)&As[kk][ty * 8];
            float4 a1 = *(const float4*)&As[kk][ty * 8 + 4];
            float4 b0 = *(const float4*)&Ws[kk][tx * 4];
            float av[8] = {a0.x, a0.y, a0.z, a0.w, a1.x, a1.y, a1.z, a1.w};
            float bv[4] = {b0.x, b0.y, b0.z, b0.w};
#pragma unroll
            for (int i = 0; i < 8; i++)
#pragma unroll
                for (int j = 0; j < 4; j++)
                    acc[i][j] = fmaf(av[i], bv[j], acc[i][j]);
        }
        __syncthreads();
    }

#pragma unroll
    for (int i = 0; i < 8; i++) {
        int r = row0 + ty * 8 + i;
        if (r >= NN) continue;
        float dv = g_dinv[r];
        float* hrow = H + (size_t)r * Cpad;
#pragma unroll
        for (int j = 0; j < 4; j++) {
            int c = col0 + tx * 4 + j;
            if (c < C)         hrow[c] = acc[i][j] * dv;
            else if (c < Cpad) hrow[c] = 0.f;
        }
    }
}

// ---------------- scatter: g_acc[dst] += g_h[src] over edges ---------------
// blockDim = (64, 4): 64 lanes cover channels, 4 edges per block.
__global__ __launch_bounds__(256) void k_scatter(int C4, int Cpad)
{
    int e = blockIdx.x * 4 + threadIdx.y;
    if (e >= NE) return;
    int2 sd = g_edges[e];
    const float4* hp = (const float4*)(g_h + (size_t)sd.x * Cpad);
    float* ap = g_acc + (size_t)sd.y * Cpad;
    for (int c = threadIdx.x; c < C4; c += 64) {
        float4 v = hp[c];
        atomicAdd(ap + 4 * c + 0, v.x);
        atomicAdd(ap + 4 * c + 1, v.y);
        atomicAdd(ap + 4 * c + 2, v.z);
        atomicAdd(ap + 4 * c + 3, v.w);
    }
}

// ------------- epilogue: out = act( (acc + h_selfloop) * dinv + b ) --------
__global__ void k_epi(const float* __restrict__ b,
                      float* __restrict__ outExt, int tagOut,
                      int C, int Cpad, int act)
{
    float* out = (tagOut == 1) ? g_act0 : (tagOut == 2) ? g_act1 : outExt;
    int n = blockIdx.y;
    int c = blockIdx.x * 256 + threadIdx.x;
    if (c >= C) return;
    size_t o = (size_t)n * Cpad + c;
    float v = (g_acc[o] + g_h[o]) * g_dinv[n] + b[c];
    if (act == 0) v = fmaxf(v, 0.f);
    else          v = 1.f / (1.f + expf(-v));
    out[(size_t)n * C + c] = v;
}

// ---------------------------------------------------------------------------
static void run_tower(const float* x,
                      const float* const* W, const float* const* b,
                      const int* dims, float* finalOut)
{
    const float* inExt = x;
    int tagIn = 0;
    for (int l = 0; l < 4; l++) {
        int K = dims[l];
        int C = dims[l + 1];
        int Cpad = (C + 3) & ~3;

        dim3 gg((C + BN - 1) / BN, (NN + BM - 1) / BM);
        k_gemm<<<gg, 256>>>(inExt, tagIn, W[l], K, C, Cpad);

        k_zero_acc<<<1024, 256>>>(NN * Cpad / 4);
        dim3 bs(64, 4);
        k_scatter<<<NE / 4, bs>>>(Cpad / 4, Cpad);

        int tagOut = (l == 3) ? 0 : ((l & 1) ? 2 : 1);
        dim3 ge((C + 255) / 256, NN);
        k_epi<<<ge, 256>>>(b[l], finalOut, tagOut, C, Cpad, (l == 3) ? 1 : 0);

        tagIn = tagOut;
    }
}

extern "C" void kernel_launch(void* const* d_in, const int* in_sizes, int n_in,
                              void* d_out, int out_size)
{
    const float* x = (const float*)d_in[0];
    const int* ei = (const int*)d_in[1];   // int32 OR int64 — sniffed on device

    const float* We[4] = {(const float*)d_in[2], (const float*)d_in[4],
                          (const float*)d_in[6], (const float*)d_in[8]};
    const float* be[4] = {(const float*)d_in[3], (const float*)d_in[5],
                          (const float*)d_in[7], (const float*)d_in[9]};
    const float* Wn[4] = {(const float*)d_in[10], (const float*)d_in[12],
                          (const float*)d_in[14], (const float*)d_in[16]};
    const float* bn[4] = {(const float*)d_in[11], (const float*)d_in[13],
                          (const float*)d_in[15], (const float*)d_in[17]};

    float* out = (float*)d_out;

    // edge decode + graph normalization (shared by both towers)
    k_detect<<<1, 1>>>(ei);
    k_prep<<<(NE + 255) / 256, 256>>>(ei);
    k_zero_deg<<<(NN + 255) / 256, 256>>>();
    k_deg<<<(NE + 255) / 256, 256>>>();
    k_dinv<<<(NN + 255) / 256, 256>>>();

    static const int dimsE[5] = {128, 166, 192, 218, 256};
    static const int dimsN[5] = {128, 128, 128, 128, 128};

    // e tower -> out[0 : NN*256]
    run_tower(x, We, be, dimsE, out);
    // v tower -> out[NN*256 : NN*256 + NN*128]
    run_tower(x, Wn, bn, dimsN, out + (size_t)NN * 256);
}

// round 5
// speedup vs baseline: 1.5315x; 1.5315x over previous
#include <cuda_runtime.h>
#include <math.h>

#define NN 50000
#define NE 400000

// ---------------- scratch (device globals; allocation-free) ----------------
__device__ __align__(16) float g_act0[NN * 256];
__device__ __align__(16) float g_act1[NN * 256];
__device__ __align__(16) float g_h[NN * 256];
__device__ float g_dinv[NN];
__device__ int   g_deg[NN];
__device__ int2  g_edges[NE];     // decoded (src, dst)
__device__ int   g_rowptr[NN + 1];
__device__ int   g_cursor[NN];
__device__ int   g_col[NE];       // CSR by dst: src indices
__device__ int   g_is64;

// ---------------- edge dtype sniff + decode ----------------
__global__ void k_detect(const int* __restrict__ e) {
    int all0 = 1;
    for (int i = 0; i < 128; i++)
        if (e[2 * i + 1] != 0) { all0 = 0; break; }
    g_is64 = all0;
}

__global__ void k_prep(const int* __restrict__ e) {
    int i = blockIdx.x * 256 + threadIdx.x;
    if (i >= NE) return;
    int s, d;
    if (g_is64) { s = e[2 * i]; d = e[2 * (NE + i)]; }
    else        { s = e[i];     d = e[NE + i]; }
    s = min(max(s, 0), NN - 1);
    d = min(max(d, 0), NN - 1);
    g_edges[i] = make_int2(s, d);
}

// ---------------- degree / dinv / CSR build ----------------
__global__ void k_zero_deg() {
    int i = blockIdx.x * 256 + threadIdx.x;
    if (i < NN) g_deg[i] = 0;
}

__global__ void k_deg() {
    int i = blockIdx.x * 256 + threadIdx.x;
    if (i < NE) atomicAdd(&g_deg[g_edges[i].y], 1);
}

__global__ void k_dinv() {
    int i = blockIdx.x * 256 + threadIdx.x;
    if (i < NN) g_dinv[i] = rsqrtf((float)(g_deg[i] + 1));  // +1 self loop
}

// exclusive scan of g_deg -> g_rowptr / g_cursor; single block of 1024
__global__ __launch_bounds__(1024) void k_scan() {
    __shared__ int ssum[1024];
    const int t = threadIdx.x;
    const int CH = (NN + 1023) / 1024;          // 49
    int beg = t * CH;
    int end = min(beg + CH, NN);
    int s = 0;
    for (int i = beg; i < end; i++) s += g_deg[i];
    ssum[t] = s;
    __syncthreads();
    // Hillis-Steele inclusive scan
    for (int off = 1; off < 1024; off <<= 1) {
        int v = ssum[t];
        int u = (t >= off) ? ssum[t - off] : 0;
        __syncthreads();
        ssum[t] = v + u;
        __syncthreads();
    }
    int run = (t == 0) ? 0 : ssum[t - 1];
    for (int i = beg; i < end; i++) {
        g_rowptr[i] = run;
        g_cursor[i] = run;
        run += g_deg[i];
    }
    if (t == 1023) g_rowptr[NN] = run;          // == NE
}

__global__ void k_place() {
    int i = blockIdx.x * 256 + threadIdx.x;
    if (i >= NE) return;
    int2 sd = g_edges[i];
    int pos = atomicAdd(&g_cursor[sd.y], 1);
    g_col[pos] = sd.x;
}

// ---------------- GEMM:  g_h[n,c] = dinv[n] * sum_k A[n,k] * W[k,c] --------
#define BM 128
#define BN 64
#define BK 16

__global__ __launch_bounds__(256) void k_gemm(
    const float* __restrict__ Aext, int tagA,
    const float* __restrict__ W, int K, int C, int Cpad)
{
    const float* A = (tagA == 1) ? g_act0 : (tagA == 2) ? g_act1 : Aext;
    float* H = g_h;

    __shared__ float As[BK][132];
    __shared__ float Ws[BK][BN];

    const int tid = threadIdx.x;
    const int tx = tid & 15;
    const int ty = tid >> 4;
    const int row0 = blockIdx.y * BM;
    const int col0 = blockIdx.x * BN;

    float acc[8][4];
#pragma unroll
    for (int i = 0; i < 8; i++)
#pragma unroll
        for (int j = 0; j < 4; j++) acc[i][j] = 0.f;

    for (int kt = 0; kt < K; kt += BK) {
#pragma unroll
        for (int s = 0; s < 8; s++) {
            int l = tid + s * 256;
            int r = l >> 4;
            int k = l & 15;
            int grow = row0 + r;
            int gk = kt + k;
            float v = 0.f;
            if (grow < NN && gk < K) v = A[(size_t)grow * K + gk];
            As[k][r] = v;
        }
#pragma unroll
        for (int s = 0; s < 4; s++) {
            int l = tid + s * 256;
            int kr = l >> 6;
            int c  = l & 63;
            int gk = kt + kr;
            int gc = col0 + c;
            float v = 0.f;
            if (gk < K && gc < C) v = W[(size_t)gk * C + gc];
            Ws[kr][c] = v;
        }
        __syncthreads();

#pragma unroll
        for (int kk = 0; kk < BK; kk++) {
            float4 a0 = *(const float4*)&As[kk][ty * 8];
            float4 a1 = *(const float4*)&As[kk][ty * 8 + 4];
            float4 b0 = *(const float4*)&Ws[kk][tx * 4];
            float av[8] = {a0.x, a0.y, a0.z, a0.w, a1.x, a1.y, a1.z, a1.w};
            float bv[4] = {b0.x, b0.y, b0.z, b0.w};
#pragma unroll
            for (int i = 0; i < 8; i++)
#pragma unroll
                for (int j = 0; j < 4; j++)
                    acc[i][j] = fmaf(av[i], bv[j], acc[i][j]);
        }
        __syncthreads();
    }

#pragma unroll
    for (int i = 0; i < 8; i++) {
        int r = row0 + ty * 8 + i;
        if (r >= NN) continue;
        float dv = g_dinv[r];
        float* hrow = H + (size_t)r * Cpad;
#pragma unroll
        for (int j = 0; j < 4; j++) {
            int c = col0 + tx * 4 + j;
            if (c < C)         hrow[c] = acc[i][j] * dv;
            else if (c < Cpad) hrow[c] = 0.f;
        }
    }
}

// -------- fused gather + self-loop + bias + activation --------------------
// out[d,c] = act( ( sum_{e in CSR[d]} H[col[e],c]  +  H[d,c] ) * dinv[d] + b[c] )
// one block per destination node; one thread per channel.
__global__ void k_gather(const float* __restrict__ b,
                         float* __restrict__ outExt, int tagOut,
                         int C, int Cpad, int act)
{
    __shared__ int scol[96];
    float* out = (tagOut == 1) ? g_act0 : (tagOut == 2) ? g_act1 : outExt;

    const int d = blockIdx.x;
    const int beg = g_rowptr[d];
    const int deg = g_rowptr[d + 1] - beg;
    const int c = threadIdx.x;

    float s = 0.f;
    int done = 0;
    while (done < deg) {
        int chunk = min(deg - done, 96);
        for (int i = threadIdx.x; i < chunk; i += blockDim.x)
            scol[i] = g_col[beg + done + i];
        __syncthreads();
        if (c < C) {
            for (int i = 0; i < chunk; i++)
                s += g_h[(size_t)scol[i] * Cpad + c];
        }
        __syncthreads();
        done += chunk;
    }
    if (c < C) {
        float v = (s + g_h[(size_t)d * Cpad + c]) * g_dinv[d] + b[c];
        if (act == 0) v = fmaxf(v, 0.f);
        else          v = 1.f / (1.f + expf(-v));
        out[(size_t)d * C + c] = v;
    }
}

// ---------------------------------------------------------------------------
static void run_tower(const float* x,
                      const float* const* W, const float* const* b,
                      const int* dims, float* finalOut)
{
    const float* inExt = x;
    int tagIn = 0;
    for (int l = 0; l < 4; l++) {
        int K = dims[l];
        int C = dims[l + 1];
        int Cpad = (C + 3) & ~3;

        dim3 gg((C + BN - 1) / BN, (NN + BM - 1) / BM);
        k_gemm<<<gg, 256>>>(inExt, tagIn, W[l], K, C, Cpad);

        int tagOut = (l == 3) ? 0 : ((l & 1) ? 2 : 1);
        int bt = ((C + 31) / 32) * 32;   // thread count covering channels
        k_gather<<<NN, bt>>>(b[l], finalOut, tagOut, C, Cpad, (l == 3) ? 1 : 0);

        tagIn = tagOut;
    }
}

extern "C" void kernel_launch(void* const* d_in, const int* in_sizes, int n_in,
                              void* d_out, int out_size)
{
    const float* x = (const float*)d_in[0];
    const int* ei = (const int*)d_in[1];   // int32 OR int64 — sniffed on device

    const float* We[4] = {(const float*)d_in[2], (const float*)d_in[4],
                          (const float*)d_in[6], (const float*)d_in[8]};
    const float* be[4] = {(const float*)d_in[3], (const float*)d_in[5],
                          (const float*)d_in[7], (const float*)d_in[9]};
    const float* Wn[4] = {(const float*)d_in[10], (const float*)d_in[12],
                          (const float*)d_in[14], (const float*)d_in[16]};
    const float* bn[4] = {(const float*)d_in[11], (const float*)d_in[13],
                          (const float*)d_in[15], (const float*)d_in[17]};

    float* out = (float*)d_out;

    // edge decode + graph normalization + CSR (shared by both towers)
    k_detect<<<1, 1>>>(ei);
    k_prep<<<(NE + 255) / 256, 256>>>(ei);
    k_zero_deg<<<(NN + 255) / 256, 256>>>();
    k_deg<<<(NE + 255) / 256, 256>>>();
    k_dinv<<<(NN + 255) / 256, 256>>>();
    k_scan<<<1, 1024>>>();
    k_place<<<(NE + 255) / 256, 256>>>();

    static const int dimsE[5] = {128, 166, 192, 218, 256};
    static const int dimsN[5] = {128, 128, 128, 128, 128};

    // e tower -> out[0 : NN*256]
    run_tower(x, We, be, dimsE, out);
    // v tower -> out[NN*256 : NN*256 + NN*128]
    run_tower(x, Wn, bn, dimsN, out + (size_t)NN * 256);
}

// round 7
// speedup vs baseline: 1.7830x; 1.1642x over previous
#include <cuda_runtime.h>
#include <math.h>
#include <stdint.h>

#define NN 50000
#define NE 400000
#define NBLK 391                 // ceil(50000/128)

// ---------------- scratch (device globals; allocation-free) ----------------
__device__ __align__(16) float g_act0[NN * 256];
__device__ __align__(16) float g_act1[NN * 256];
__device__ __align__(16) float g_h[NN * 256];        // GEMM out, stride 256
__device__ __align__(16) float g_wt_hi[256 * 224];   // W^T tf32-hi, [Npad64][Kpad]
__device__ __align__(16) float g_wt_lo[256 * 224];   // W^T tf32-lo
__device__ float g_dinv[NN];
__device__ int   g_deg[NN];
__device__ int2  g_edges[NE];
__device__ int   g_rowptr[NN + 1];
__device__ int   g_cursor[NN];
__device__ int   g_col[NE];
__device__ int   g_is64;

// ---------------- helpers ----------------
__device__ __forceinline__ float tf32r(float x) {   // round-to-nearest tf32
    uint32_t u;
    asm("cvt.rna.tf32.f32 %0, %1;" : "=r"(u) : "f"(x));
    return __uint_as_float(u);
}
__device__ __forceinline__ void mma8(float* c, const uint32_t* a, const uint32_t* b) {
    asm volatile(
        "mma.sync.aligned.m16n8k8.row.col.f32.tf32.tf32.f32 "
        "{%0,%1,%2,%3}, {%4,%5,%6,%7}, {%8,%9}, {%0,%1,%2,%3};"
        : "+f"(c[0]), "+f"(c[1]), "+f"(c[2]), "+f"(c[3])
        : "r"(a[0]), "r"(a[1]), "r"(a[2]), "r"(a[3]), "r"(b[0]), "r"(b[1]));
}

// ---------------- edge dtype sniff + decode ----------------
__global__ void k_detect(const int* __restrict__ e) {
    int all0 = 1;
    for (int i = 0; i < 128; i++)
        if (e[2 * i + 1] != 0) { all0 = 0; break; }
    g_is64 = all0;
}

__global__ void k_prep(const int* __restrict__ e) {
    int i = blockIdx.x * 256 + threadIdx.x;
    if (i >= NE) return;
    int s, d;
    if (g_is64) { s = e[2 * i]; d = e[2 * (NE + i)]; }
    else        { s = e[i];     d = e[NE + i]; }
    s = min(max(s, 0), NN - 1);
    d = min(max(d, 0), NN - 1);
    g_edges[i] = make_int2(s, d);
}

// ---------------- degree / dinv / CSR build ----------------
__global__ void k_zero_deg() {
    int i = blockIdx.x * 256 + threadIdx.x;
    if (i < NN) g_deg[i] = 0;
}
__global__ void k_deg() {
    int i = blockIdx.x * 256 + threadIdx.x;
    if (i < NE) atomicAdd(&g_deg[g_edges[i].y], 1);
}
__global__ void k_dinv() {
    int i = blockIdx.x * 256 + threadIdx.x;
    if (i < NN) g_dinv[i] = rsqrtf((float)(g_deg[i] + 1));
}

__global__ __launch_bounds__(1024) void k_scan() {
    __shared__ int ssum[1024];
    const int t = threadIdx.x;
    const int CH = (NN + 1023) / 1024;
    int beg = t * CH;
    int end = min(beg + CH, NN);
    int s = 0;
    for (int i = beg; i < end; i++) s += g_deg[i];
    ssum[t] = s;
    __syncthreads();
    for (int off = 1; off < 1024; off <<= 1) {
        int v = ssum[t];
        int u = (t >= off) ? ssum[t - off] : 0;
        __syncthreads();
        ssum[t] = v + u;
        __syncthreads();
    }
    int run = (t == 0) ? 0 : ssum[t - 1];
    for (int i = beg; i < end; i++) {
        g_rowptr[i] = run;
        g_cursor[i] = run;
        run += g_deg[i];
    }
    if (t == 1023) g_rowptr[NN] = run;
}

__global__ void k_place() {
    int i = blockIdx.x * 256 + threadIdx.x;
    if (i >= NE) return;
    int2 sd = g_edges[i];
    int pos = atomicAdd(&g_cursor[sd.y], 1);
    g_col[pos] = sd.x;
}

// -------- W prep: transpose + tf32 hi/lo split + zero-pad -------------------
// g_wt_hi/lo[n][k] for n<Npad64, k<Kpad  (= W[k][n] if in-range, else 0)
__global__ void k_wprep(const float* __restrict__ W, int K, int C,
                        int Kpad, int Npad64) {
    int i = blockIdx.x * 256 + threadIdx.x;
    if (i >= Npad64 * Kpad) return;
    int n = i / Kpad, k = i % Kpad;
    float w = (n < C && k < K) ? W[(size_t)k * C + n] : 0.f;
    float hi = tf32r(w);
    g_wt_hi[i] = hi;
    g_wt_lo[i] = tf32r(w - hi);
}

// -------- mma.sync tf32 GEMM (3x split): g_h = dinv * (A @ W) ---------------
// A: [NN, lda] fp32 (lda == Kpad, pad cols zero). Out stride fixed 256.
// block 256 thr = 8 warps (4 M x 2 N); tile 128 x 64 x 32.
#define SM_AS 4608            // 128*36 floats
#define SM_BS 2304            // 64*36 floats
#define SMEM_TC ((2 * SM_AS + 2 * SM_BS) * 4)

__global__ __launch_bounds__(256) void k_gemm_tc(
    const float* __restrict__ Aext, int tagA, int lda, int Kpad, int C)
{
    extern __shared__ float sm[];
    float* As_hi = sm;
    float* As_lo = sm + SM_AS;
    float* Bs_hi = sm + 2 * SM_AS;
    float* Bs_lo = sm + 2 * SM_AS + SM_BS;

    const float* A = (tagA == 1) ? g_act0 : (tagA == 2) ? g_act1 : Aext;
    const int tid = threadIdx.x;
    const int wid = tid >> 5, lid = tid & 31;
    const int warpM = wid & 3, warpN = wid >> 2;
    const int g = lid >> 2, tg = lid & 3;
    const int row0 = blockIdx.y * 128;
    const int col0 = blockIdx.x * 64;

    float acc[2][4][4];
#pragma unroll
    for (int mt = 0; mt < 2; mt++)
#pragma unroll
        for (int nt = 0; nt < 4; nt++)
#pragma unroll
            for (int j = 0; j < 4; j++) acc[mt][nt][j] = 0.f;

    for (int kt = 0; kt < Kpad; kt += 32) {
        // stage A: 128 rows x 32 cols, split hi/lo
#pragma unroll
        for (int i = 0; i < 4; i++) {
            int l = tid + i * 256;
            int r = l >> 3;
            int k4 = (l & 7) << 2;
            int gr = row0 + r; if (gr > NN - 1) gr = NN - 1;
            float4 v = *(const float4*)(A + (size_t)gr * lda + kt + k4);
            float4 hi, lo;
            hi.x = tf32r(v.x); lo.x = tf32r(v.x - hi.x);
            hi.y = tf32r(v.y); lo.y = tf32r(v.y - hi.y);
            hi.z = tf32r(v.z); lo.z = tf32r(v.z - hi.z);
            hi.w = tf32r(v.w); lo.w = tf32r(v.w - hi.w);
            *(float4*)(As_hi + r * 36 + k4) = hi;
            *(float4*)(As_lo + r * 36 + k4) = lo;
        }
        // stage B: 64 n-rows x 32 k (pre-split in gmem)
#pragma unroll
        for (int i = 0; i < 2; i++) {
            int l = tid + i * 256;
            int n = l >> 3;
            int k4 = (l & 7) << 2;
            size_t go = (size_t)(col0 + n) * Kpad + kt + k4;
            *(float4*)(Bs_hi + n * 36 + k4) = *(const float4*)(g_wt_hi + go);
            *(float4*)(Bs_lo + n * 36 + k4) = *(const float4*)(g_wt_lo + go);
        }
        __syncthreads();

#pragma unroll
        for (int ks = 0; ks < 4; ks++) {
            const int kk = ks * 8;
            uint32_t ah[2][4], al[2][4], bh[4][2], bl[4][2];
#pragma unroll
            for (int mt = 0; mt < 2; mt++) {
                int rb = warpM * 32 + mt * 16;
                ah[mt][0] = __float_as_uint(As_hi[(rb + g)     * 36 + kk + tg]);
                ah[mt][1] = __float_as_uint(As_hi[(rb + g + 8) * 36 + kk + tg]);
                ah[mt][2] = __float_as_uint(As_hi[(rb + g)     * 36 + kk + tg + 4]);
                ah[mt][3] = __float_as_uint(As_hi[(rb + g + 8) * 36 + kk + tg + 4]);
                al[mt][0] = __float_as_uint(As_lo[(rb + g)     * 36 + kk + tg]);
                al[mt][1] = __float_as_uint(As_lo[(rb + g + 8) * 36 + kk + tg]);
                al[mt][2] = __float_as_uint(As_lo[(rb + g)     * 36 + kk + tg + 4]);
                al[mt][3] = __float_as_uint(As_lo[(rb + g + 8) * 36 + kk + tg + 4]);
            }
#pragma unroll
            for (int nt = 0; nt < 4; nt++) {
                int cb = warpN * 32 + nt * 8;
                bh[nt][0] = __float_as_uint(Bs_hi[(cb + g) * 36 + kk + tg]);
                bh[nt][1] = __float_as_uint(Bs_hi[(cb + g) * 36 + kk + tg + 4]);
                bl[nt][0] = __float_as_uint(Bs_lo[(cb + g) * 36 + kk + tg]);
                bl[nt][1] = __float_as_uint(Bs_lo[(cb + g) * 36 + kk + tg + 4]);
            }
#pragma unroll
            for (int mt = 0; mt < 2; mt++)
#pragma unroll
                for (int nt = 0; nt < 4; nt++) {
                    mma8(acc[mt][nt], ah[mt], bh[nt]);
                    mma8(acc[mt][nt], ah[mt], bl[nt]);
                    mma8(acc[mt][nt], al[mt], bh[nt]);
                }
        }
        __syncthreads();
    }

    // epilogue: * dinv -> g_h (stride 256)
#pragma unroll
    for (int mt = 0; mt < 2; mt++) {
#pragma unroll
        for (int half = 0; half < 2; half++) {
            int r = row0 + warpM * 32 + mt * 16 + g + half * 8;
            if (r >= NN) continue;
            float dv = g_dinv[r];
#pragma unroll
            for (int nt = 0; nt < 4; nt++) {
                int c = col0 + warpN * 32 + nt * 8 + tg * 2;
                float v0 = acc[mt][nt][half * 2 + 0] * dv;
                float v1 = acc[mt][nt][half * 2 + 1] * dv;
                if (c < C)     g_h[(size_t)r * 256 + c] = v0;
                if (c + 1 < C) g_h[(size_t)r * 256 + c + 1] = v1;
            }
        }
    }
}

// -------- fused gather + self-loop + bias + activation ----------------------
__global__ void k_gather(const float* __restrict__ b,
                         float* __restrict__ outExt, int tagOut,
                         int C, int Cpad, int act)
{
    __shared__ int scol[96];
    float* out = (tagOut == 1) ? g_act0 : (tagOut == 2) ? g_act1 : outExt;

    const int d = blockIdx.x;
    const int beg = g_rowptr[d];
    const int deg = g_rowptr[d + 1] - beg;
    const int c = threadIdx.x;

    float s = 0.f;
    int done = 0;
    while (done < deg) {
        int chunk = min(deg - done, 96);
        for (int i = threadIdx.x; i < chunk; i += blockDim.x)
            scol[i] = g_col[beg + done + i];
        __syncthreads();
        if (c < C) {
            for (int i = 0; i < chunk; i++)
                s += g_h[(size_t)scol[i] * 256 + c];
        }
        __syncthreads();
        done += chunk;
    }
    float v = 0.f;
    if (c < C) {
        v = (s + g_h[(size_t)d * 256 + c]) * g_dinv[d] + b[c];
        if (act == 0) v = fmaxf(v, 0.f);
        else          v = 1.f / (1.f + expf(-v));
    }
    out[(size_t)d * Cpad + c] = v;
}

// ---------------------------------------------------------------------------
static void run_tower(const float* x,
                      const float* const* W, const float* const* b,
                      const int* Kd, const int* Cd, float* finalOut)
{
    const float* inExt = x;
    int tagIn = 0;
    for (int l = 0; l < 4; l++) {
        int K = Kd[l], C = Cd[l];
        int Kpad = (K + 31) & ~31;
        int Npad64 = (C + 63) & ~63;
        int Cpad = (C + 31) & ~31;

        k_wprep<<<(Npad64 * Kpad + 255) / 256, 256>>>(W[l], K, C, Kpad, Npad64);
        dim3 gg(Npad64 / 64, NBLK);
        k_gemm_tc<<<gg, 256, SMEM_TC>>>(inExt, tagIn, Kpad, Kpad, C);

        int tagOut = (l == 3) ? 0 : ((l & 1) ? 2 : 1);
        k_gather<<<NN, Cpad>>>(b[l], finalOut, tagOut, C, Cpad, (l == 3) ? 1 : 0);
        tagIn = tagOut;
    }
}

extern "C" void kernel_launch(void* const* d_in, const int* in_sizes, int n_in,
                              void* d_out, int out_size)
{
    const float* x = (const float*)d_in[0];
    const int* ei = (const int*)d_in[1];

    const float* We[4] = {(const float*)d_in[2], (const float*)d_in[4],
                          (const float*)d_in[6], (const float*)d_in[8]};
    const float* be[4] = {(const float*)d_in[3], (const float*)d_in[5],
                          (const float*)d_in[7], (const float*)d_in[9]};
    const float* Wn[4] = {(const float*)d_in[10], (const float*)d_in[12],
                          (const float*)d_in[14], (const float*)d_in[16]};
    const float* bn[4] = {(const float*)d_in[11], (const float*)d_in[13],
                          (const float*)d_in[15], (const float*)d_in[17]};

    float* out = (float*)d_out;

    cudaFuncSetAttribute(k_gemm_tc, cudaFuncAttributeMaxDynamicSharedMemorySize,
                         SMEM_TC);

    // edge decode + graph normalization + CSR (shared by both towers)
    k_detect<<<1, 1>>>(ei);
    k_prep<<<(NE + 255) / 256, 256>>>(ei);
    k_zero_deg<<<(NN + 255) / 256, 256>>>();
    k_deg<<<(NE + 255) / 256, 256>>>();
    k_dinv<<<(NN + 255) / 256, 256>>>();
    k_scan<<<1, 1024>>>();
    k_place<<<(NE + 255) / 256, 256>>>();

    static const int Ke[4] = {128, 166, 192, 218};
    static const int Ce[4] = {166, 192, 218, 256};
    static const int Kn[4] = {128, 128, 128, 128};
    static const int Cn[4] = {128, 128, 128, 128};

    // e tower -> out[0 : NN*256]
    run_tower(x, We, be, Ke, Ce, out);
    // v tower -> out[NN*256 : NN*256 + NN*128]
    run_tower(x, Wn, bn, Kn, Cn, out + (size_t)NN * 256);
}

// round 8
// speedup vs baseline: 2.2788x; 1.2780x over previous
#include <cuda_runtime.h>
#include <math.h>
#include <stdint.h>

#define NN 50000
#define NE 400000
#define NBLK 391                 // ceil(50000/128)

// ---------------- scratch (device globals; allocation-free) ----------------
__device__ __align__(16) float g_a_hi[NN * 256];     // activation, tf32-hi, stride 256
__device__ __align__(16) float g_a_lo[NN * 256];     // activation, tf32-lo
__device__ __align__(16) float g_h[NN * 256];        // GEMM out, stride 256
__device__ __align__(16) float g_wt_hi[256 * 224];   // W^T tf32-hi, [Npad64][Kpad16]
__device__ __align__(16) float g_wt_lo[256 * 224];
__device__ float g_dinv[NN];
__device__ int   g_deg[NN];
__device__ int2  g_edges[NE];
__device__ int   g_rowptr[NN + 1];
__device__ int   g_cursor[NN];
__device__ int   g_col[NE];
__device__ int   g_is64;

// ---------------- helpers ----------------
__device__ __forceinline__ float tf32r(float x) {
    uint32_t u;
    asm("cvt.rna.tf32.f32 %0, %1;" : "=r"(u) : "f"(x));
    return __uint_as_float(u);
}
__device__ __forceinline__ void mma8(float* c, const uint32_t* a, const uint32_t* b) {
    asm volatile(
        "mma.sync.aligned.m16n8k8.row.col.f32.tf32.tf32.f32 "
        "{%0,%1,%2,%3}, {%4,%5,%6,%7}, {%8,%9}, {%0,%1,%2,%3};"
        : "+f"(c[0]), "+f"(c[1]), "+f"(c[2]), "+f"(c[3])
        : "r"(a[0]), "r"(a[1]), "r"(a[2]), "r"(a[3]), "r"(b[0]), "r"(b[1]));
}
__device__ __forceinline__ void cpa16(uint32_t s, const void* g) {
    asm volatile("cp.async.ca.shared.global [%0], [%1], 16;" :: "r"(s), "l"(g));
}
#define CP_COMMIT() asm volatile("cp.async.commit_group;" ::: "memory")
#define CP_WAIT1()  asm volatile("cp.async.wait_group 1;" ::: "memory")

// ---------------- edge dtype sniff + decode ----------------
__global__ void k_detect(const int* __restrict__ e) {
    int all0 = 1;
    for (int i = 0; i < 128; i++)
        if (e[2 * i + 1] != 0) { all0 = 0; break; }
    g_is64 = all0;
}

__global__ void k_prep(const int* __restrict__ e) {
    int i = blockIdx.x * 256 + threadIdx.x;
    if (i >= NE) return;
    int s, d;
    if (g_is64) { s = e[2 * i]; d = e[2 * (NE + i)]; }
    else        { s = e[i];     d = e[NE + i]; }
    s = min(max(s, 0), NN - 1);
    d = min(max(d, 0), NN - 1);
    g_edges[i] = make_int2(s, d);
}

// ---------------- degree / dinv / CSR build ----------------
__global__ void k_zero_deg() {
    int i = blockIdx.x * 256 + threadIdx.x;
    if (i < NN) g_deg[i] = 0;
}
__global__ void k_deg() {
    int i = blockIdx.x * 256 + threadIdx.x;
    if (i < NE) atomicAdd(&g_deg[g_edges[i].y], 1);
}
__global__ void k_dinv() {
    int i = blockIdx.x * 256 + threadIdx.x;
    if (i < NN) g_dinv[i] = rsqrtf((float)(g_deg[i] + 1));
}

__global__ __launch_bounds__(1024) void k_scan() {
    __shared__ int ssum[1024];
    const int t = threadIdx.x;
    const int CH = (NN + 1023) / 1024;
    int beg = t * CH;
    int end = min(beg + CH, NN);
    int s = 0;
    for (int i = beg; i < end; i++) s += g_deg[i];
    ssum[t] = s;
    __syncthreads();
    for (int off = 1; off < 1024; off <<= 1) {
        int v = ssum[t];
        int u = (t >= off) ? ssum[t - off] : 0;
        __syncthreads();
        ssum[t] = v + u;
        __syncthreads();
    }
    int run = (t == 0) ? 0 : ssum[t - 1];
    for (int i = beg; i < end; i++) {
        g_rowptr[i] = run;
        g_cursor[i] = run;
        run += g_deg[i];
    }
    if (t == 1023) g_rowptr[NN] = run;
}

__global__ void k_place() {
    int i = blockIdx.x * 256 + threadIdx.x;
    if (i >= NE) return;
    int2 sd = g_edges[i];
    int pos = atomicAdd(&g_cursor[sd.y], 1);
    g_col[pos] = sd.x;
}

// -------- x split: g_a_hi/lo[n][0:128] = tf32 split of x --------------------
__global__ void k_xsplit(const float* __restrict__ x) {
    int i = blockIdx.x * 256 + threadIdx.x;      // quad index
    if (i >= NN * 32) return;
    int n = i >> 5, q = (i & 31) << 2;
    float4 v = *(const float4*)(x + (size_t)n * 128 + q);
    float4 hi, lo;
    hi.x = tf32r(v.x); lo.x = tf32r(v.x - hi.x);
    hi.y = tf32r(v.y); lo.y = tf32r(v.y - hi.y);
    hi.z = tf32r(v.z); lo.z = tf32r(v.z - hi.z);
    hi.w = tf32r(v.w); lo.w = tf32r(v.w - hi.w);
    *(float4*)(g_a_hi + (size_t)n * 256 + q) = hi;
    *(float4*)(g_a_lo + (size_t)n * 256 + q) = lo;
}

// -------- W prep: transpose + tf32 hi/lo split + zero-pad -------------------
__global__ void k_wprep(const float* __restrict__ W, int K, int C,
                        int Kpad, int Npad64) {
    int i = blockIdx.x * 256 + threadIdx.x;
    if (i >= Npad64 * Kpad) return;
    int n = i / Kpad, k = i % Kpad;
    float w = (n < C && k < K) ? W[(size_t)k * C + n] : 0.f;
    float hi = tf32r(w);
    g_wt_hi[i] = hi;
    g_wt_lo[i] = tf32r(w - hi);
}

// -------- cp.async double-buffered tf32 GEMM (3x split) ---------------------
// tile 128 x 64 x 16; 8 warps (4M x 2N); A from g_a_hi/lo (stride 256).
// stage layout (floats): AH[128][20] AL[128][20] BH[64][20] BL[64][20] = 7680
#define STG 7680
#define SMEM_TC (2 * STG * 4)

__global__ __launch_bounds__(256) void k_gemm_tc(int ldb, int Kpad, int C)
{
    extern __shared__ float sm[];
    const int tid = threadIdx.x;
    const int wid = tid >> 5, lid = tid & 31;
    const int warpM = wid & 3, warpN = wid >> 2;
    const int g = lid >> 2, tg = lid & 3;
    const int row0 = blockIdx.y * 128;
    const int col0 = blockIdx.x * 64;
    const uint32_t sb = (uint32_t)__cvta_generic_to_shared(sm);

    // per-thread staging coords (constant across chunks)
    //   A: 4 quads; l = tid + i*256, mat = l>=512 (lo), r = (l&511)>>2, q=(l&3)*4
    //   B: 2 quads; l = tid + i*256, mat = l>=256 (lo), r = (l&255)>>2, q=(l&3)*4
    const float* aSrc[4]; uint32_t aDst[4];
    const float* bSrc[2]; uint32_t bDst[2];
#pragma unroll
    for (int i = 0; i < 4; i++) {
        int l = tid + i * 256;
        int r = (l & 511) >> 2, q = (l & 3) << 2;
        int gr = row0 + r; if (gr > NN - 1) gr = NN - 1;
        aSrc[i] = ((l < 512) ? g_a_hi : g_a_lo) + (size_t)gr * 256 + q;
        aDst[i] = (uint32_t)(((l < 512) ? 0 : 2560) + r * 20 + q) * 4;
    }
#pragma unroll
    for (int i = 0; i < 2; i++) {
        int l = tid + i * 256;
        int r = (l & 255) >> 2, q = (l & 3) << 2;
        bSrc[i] = ((l < 256) ? g_wt_hi : g_wt_lo) + (size_t)(col0 + r) * ldb + q;
        bDst[i] = (uint32_t)(((l < 256) ? 5120 : 6400) + r * 20 + q) * 4;
    }

    float acc[2][4][4];
#pragma unroll
    for (int mt = 0; mt < 2; mt++)
#pragma unroll
        for (int nt = 0; nt < 4; nt++)
#pragma unroll
            for (int j = 0; j < 4; j++) acc[mt][nt][j] = 0.f;

    const int nch = Kpad >> 4;

    // prefetch chunk 0 into stage 0
#pragma unroll
    for (int i = 0; i < 4; i++) cpa16(sb + aDst[i], aSrc[i]);
#pragma unroll
    for (int i = 0; i < 2; i++) cpa16(sb + bDst[i], bSrc[i]);
    CP_COMMIT();

    for (int ch = 0; ch < nch; ch++) {
        const uint32_t stOff = (uint32_t)(ch & 1) * (STG * 4);
        if (ch + 1 < nch) {
            const uint32_t nOff = (uint32_t)((ch + 1) & 1) * (STG * 4);
            const int kt = (ch + 1) << 4;
#pragma unroll
            for (int i = 0; i < 4; i++) cpa16(sb + nOff + aDst[i], aSrc[i] + kt);
#pragma unroll
            for (int i = 0; i < 2; i++) cpa16(sb + nOff + bDst[i], bSrc[i] + kt);
        }
        CP_COMMIT();
        CP_WAIT1();
        __syncthreads();

        const float* As_hi = sm + (ch & 1) * STG;
        const float* As_lo = As_hi + 2560;
        const float* Bs_hi = As_hi + 5120;
        const float* Bs_lo = As_hi + 6400;
        (void)stOff;

#pragma unroll
        for (int ks = 0; ks < 2; ks++) {
            const int kk = ks * 8;
            uint32_t ah[2][4], al[2][4], bh[4][2], bl[4][2];
#pragma unroll
            for (int mt = 0; mt < 2; mt++) {
                int rb = warpM * 32 + mt * 16;
                ah[mt][0] = __float_as_uint(As_hi[(rb + g)     * 20 + kk + tg]);
                ah[mt][1] = __float_as_uint(As_hi[(rb + g + 8) * 20 + kk + tg]);
                ah[mt][2] = __float_as_uint(As_hi[(rb + g)     * 20 + kk + tg + 4]);
                ah[mt][3] = __float_as_uint(As_hi[(rb + g + 8) * 20 + kk + tg + 4]);
                al[mt][0] = __float_as_uint(As_lo[(rb + g)     * 20 + kk + tg]);
                al[mt][1] = __float_as_uint(As_lo[(rb + g + 8) * 20 + kk + tg]);
                al[mt][2] = __float_as_uint(As_lo[(rb + g)     * 20 + kk + tg + 4]);
                al[mt][3] = __float_as_uint(As_lo[(rb + g + 8) * 20 + kk + tg + 4]);
            }
#pragma unroll
            for (int nt = 0; nt < 4; nt++) {
                int cb = warpN * 32 + nt * 8;
                bh[nt][0] = __float_as_uint(Bs_hi[(cb + g) * 20 + kk + tg]);
                bh[nt][1] = __float_as_uint(Bs_hi[(cb + g) * 20 + kk + tg + 4]);
                bl[nt][0] = __float_as_uint(Bs_lo[(cb + g) * 20 + kk + tg]);
                bl[nt][1] = __float_as_uint(Bs_lo[(cb + g) * 20 + kk + tg + 4]);
            }
#pragma unroll
            for (int mt = 0; mt < 2; mt++)
#pragma unroll
                for (int nt = 0; nt < 4; nt++) {
                    mma8(acc[mt][nt], ah[mt], bh[nt]);
                    mma8(acc[mt][nt], ah[mt], bl[nt]);
                    mma8(acc[mt][nt], al[mt], bh[nt]);
                }
        }
        __syncthreads();
    }

    // epilogue: * dinv -> g_h (stride 256); pad cols (>=C) zero-filled
#pragma unroll
    for (int mt = 0; mt < 2; mt++) {
#pragma unroll
        for (int half = 0; half < 2; half++) {
            int r = row0 + warpM * 32 + mt * 16 + g + half * 8;
            if (r >= NN) continue;
            float dv = g_dinv[r];
#pragma unroll
            for (int nt = 0; nt < 4; nt++) {
                int c = col0 + warpN * 32 + nt * 8 + tg * 2;
                float v0 = (c < C)     ? acc[mt][nt][half * 2 + 0] * dv : 0.f;
                float v1 = (c + 1 < C) ? acc[mt][nt][half * 2 + 1] * dv : 0.f;
                g_h[(size_t)r * 256 + c]     = v0;
                g_h[(size_t)r * 256 + c + 1] = v1;
            }
        }
    }
}

// -------- fused gather + self-loop + bias + act + tf32 split ----------------
// 64 threads/block, one node/block, thread = 4 channels (float4).
__global__ __launch_bounds__(64) void k_gather4(
    const float* __restrict__ bias, float* __restrict__ outExt,
    int isFinal, int C, int Cpad, int act)
{
    __shared__ int scol[64];
    const int d = blockIdx.x;
    const int beg = g_rowptr[d];
    const int deg = g_rowptr[d + 1] - beg;
    const int c4 = threadIdx.x << 2;

    float4 s = make_float4(0.f, 0.f, 0.f, 0.f);
    for (int done = 0; done < deg; done += 64) {
        int chunk = min(deg - done, 64);
        if (threadIdx.x < chunk) scol[threadIdx.x] = g_col[beg + done + threadIdx.x];
        __syncthreads();
        if (c4 < C) {
            for (int i = 0; i < chunk; i++) {
                float4 v = *(const float4*)(g_h + (size_t)scol[i] * 256 + c4);
                s.x += v.x; s.y += v.y; s.z += v.z; s.w += v.w;
            }
        }
        __syncthreads();
    }
    if (c4 >= Cpad) return;

    const float dv = g_dinv[d];
    float4 h = *(const float4*)(g_h + (size_t)d * 256 + c4);
    float val[4] = {(s.x + h.x) * dv, (s.y + h.y) * dv,
                    (s.z + h.z) * dv, (s.w + h.w) * dv};
#pragma unroll
    for (int j = 0; j < 4; j++) {
        int c = c4 + j;
        float v = 0.f;
        if (c < C) {
            v = val[j] + bias[c];
            if (act == 0) v = fmaxf(v, 0.f);
            else          v = 1.f / (1.f + expf(-v));
        }
        val[j] = v;
    }
    if (isFinal) {
        if (c4 < C)   // final C is a multiple of 4
            *(float4*)(outExt + (size_t)d * C + c4) =
                make_float4(val[0], val[1], val[2], val[3]);
    } else {
        float4 hi, lo;
        hi.x = tf32r(val[0]); lo.x = tf32r(val[0] - hi.x);
        hi.y = tf32r(val[1]); lo.y = tf32r(val[1] - hi.y);
        hi.z = tf32r(val[2]); lo.z = tf32r(val[2] - hi.z);
        hi.w = tf32r(val[3]); lo.w = tf32r(val[3] - hi.w);
        *(float4*)(g_a_hi + (size_t)d * 256 + c4) = hi;
        *(float4*)(g_a_lo + (size_t)d * 256 + c4) = lo;
    }
}

// ---------------------------------------------------------------------------
static void run_tower(const float* x,
                      const float* const* W, const float* const* b,
                      const int* Kd, const int* Cd, float* finalOut)
{
    k_xsplit<<<(NN * 32 + 255) / 256, 256>>>(x);
    for (int l = 0; l < 4; l++) {
        int K = Kd[l], C = Cd[l];
        int Kpad = (K + 15) & ~15;
        int Npad64 = (C + 63) & ~63;
        int Cpad = (C + 31) & ~31;

        k_wprep<<<(Npad64 * Kpad + 255) / 256, 256>>>(W[l], K, C, Kpad, Npad64);
        dim3 gg(Npad64 / 64, NBLK);
        k_gemm_tc<<<gg, 256, SMEM_TC>>>(Kpad, Kpad, C);

        k_gather4<<<NN, 64>>>(b[l], finalOut, (l == 3) ? 1 : 0, C, Cpad,
                              (l == 3) ? 1 : 0);
    }
}

extern "C" void kernel_launch(void* const* d_in, const int* in_sizes, int n_in,
                              void* d_out, int out_size)
{
    const float* x = (const float*)d_in[0];
    const int* ei = (const int*)d_in[1];

    const float* We[4] = {(const float*)d_in[2], (const float*)d_in[4],
                          (const float*)d_in[6], (const float*)d_in[8]};
    const float* be[4] = {(const float*)d_in[3], (const float*)d_in[5],
                          (const float*)d_in[7], (const float*)d_in[9]};
    const float* Wn[4] = {(const float*)d_in[10], (const float*)d_in[12],
                          (const float*)d_in[14], (const float*)d_in[16]};
    const float* bn[4] = {(const float*)d_in[11], (const float*)d_in[13],
                          (const float*)d_in[15], (const float*)d_in[17]};

    float* out = (float*)d_out;

    cudaFuncSetAttribute(k_gemm_tc, cudaFuncAttributeMaxDynamicSharedMemorySize,
                         SMEM_TC);

    // edge decode + graph normalization + CSR (shared by both towers)
    k_detect<<<1, 1>>>(ei);
    k_prep<<<(NE + 255) / 256, 256>>>(ei);
    k_zero_deg<<<(NN + 255) / 256, 256>>>();
    k_deg<<<(NE + 255) / 256, 256>>>();
    k_dinv<<<(NN + 255) / 256, 256>>>();
    k_scan<<<1, 1024>>>();
    k_place<<<(NE + 255) / 256, 256>>>();

    static const int Ke[4] = {128, 166, 192, 218};
    static const int Ce[4] = {166, 192, 218, 256};
    static const int Kn[4] = {128, 128, 128, 128};
    static const int Cn[4] = {128, 128, 128, 128};

    // e tower -> out[0 : NN*256]
    run_tower(x, We, be, Ke, Ce, out);
    // v tower -> out[NN*256 : NN*256 + NN*128]
    run_tower(x, Wn, bn, Kn, Cn, out + (size_t)NN * 256);
}